// round 16
// baseline (speedup 1.0000x reference)
#include <cuda_runtime.h>

#define BB   512
#define CC   512
#define KK   512
#define EE   16
#define NT   128

#define Z_OFF   0
#define ZE_OFF  ((size_t)BB * CC * EE)            // 4,194,304 floats
#define OH_OFF  ((size_t)2 * BB * CC * EE)        // 8,388,608 floats

typedef unsigned long long u64;

__device__ __forceinline__ u64 pack2(float a, float b) {
    u64 r;
    asm("mov.b64 %0, {%1, %2};" : "=l"(r) : "f"(a), "f"(b));
    return r;
}
__device__ __forceinline__ void fma2(u64 &d, u64 a, u64 b) {
    asm("fma.rn.f32x2 %0, %1, %2, %0;" : "+l"(d) : "l"(a), "l"(b));
}
__device__ __forceinline__ void unpack2(float &lo, float &hi, u64 v) {
    asm("mov.b64 {%0, %1}, %2;" : "=f"(lo), "=f"(hi) : "l"(v));
}

// Dynamic smem (36,864 B): sdict float[KK*EE] (32 KB), snrm2 u64[KK] (4 KB, (nrm,0) pairs)
__global__ void __launch_bounds__(NT, 3) vq_kernel(const float* __restrict__ mu,
                                                   const float* __restrict__ dict,
                                                   float* __restrict__ out)
{
    extern __shared__ float smem_f[];
    float* sdict = smem_f;
    u64*   snrm2 = (u64*)(smem_f + KK * EE);

    const int c = blockIdx.x;
    const int t = threadIdx.x;

    // ---- this thread's 4 batch rows, packed pairwise over e ----
    u64 muA[EE / 2], muB[EE / 2], muC[EE / 2], muD[EE / 2];
    {
        const float* m0 = mu + (size_t)(t)       * (CC * EE) + c * EE;
        const float* m1 = mu + (size_t)(t + 128) * (CC * EE) + c * EE;
        const float* m2 = mu + (size_t)(t + 256) * (CC * EE) + c * EE;
        const float* m3 = mu + (size_t)(t + 384) * (CC * EE) + c * EE;
#pragma unroll
        for (int e = 0; e < EE; e += 4) {
            float4 a = *(const float4*)(m0 + e);
            float4 b = *(const float4*)(m1 + e);
            float4 x = *(const float4*)(m2 + e);
            float4 y = *(const float4*)(m3 + e);
            muA[e / 2] = pack2(a.x, a.y);  muA[e / 2 + 1] = pack2(a.z, a.w);
            muB[e / 2] = pack2(b.x, b.y);  muB[e / 2 + 1] = pack2(b.z, b.w);
            muC[e / 2] = pack2(x.x, x.y);  muC[e / 2 + 1] = pack2(x.z, x.w);
            muD[e / 2] = pack2(y.x, y.y);  muD[e / 2 + 1] = pack2(y.z, y.w);
        }
    }

    // ---- dict[c] -> smem (natural layout) ----
    {
        const float4* g = (const float4*)(dict + (size_t)c * KK * EE);
        float4* sd4 = (float4*)sdict;
#pragma unroll 4
        for (int i = t; i < KK * EE / 4; i += NT) sd4[i] = g[i];
    }
    __syncthreads();

    // ---- snrm2[k] = (-0.5*||d_k||^2, 0) packed ----
#pragma unroll
    for (int k = t; k < KK; k += NT) {
        const float4* dv = (const float4*)(sdict + k * EE);
        float s = 0.f;
#pragma unroll
        for (int j = 0; j < 4; j++) {
            float4 v = dv[j];
            s = fmaf(v.x, v.x, s); s = fmaf(v.y, v.y, s);
            s = fmaf(v.z, v.z, s); s = fmaf(v.w, v.w, s);
        }
        snrm2[k] = pack2(-0.5f * s, 0.0f);
    }
    __syncthreads();

    // ---- one_hot zero cursors: rows (2it, 2it+1), thread t covers col4 t ----
    const float4 z4 = make_float4(0.f, 0.f, 0.f, 0.f);
    const size_t ROWF4 = (size_t)CC * KK / 4;
    float4* ohp0 = (float4*)(out + OH_OFF) + (size_t)c * (KK / 4) + t;
    float4* ohp1 = ohp0 + ROWF4;
    const size_t OH_STEP = 2 * ROWF4;

    // ---- main argmax loop (k-pairs): 64 FFMA2 per 5 LDS ----
    float best0 = -3.4e38f, best1 = -3.4e38f, best2 = -3.4e38f, best3 = -3.4e38f;
    int i0 = 0, i1 = 0, i2 = 0, i3 = 0;
    const ulonglong2* dq = (const ulonglong2*)sdict;    // 8 per k-pair

#pragma unroll 2
    for (int it = 0; it < KK / 2; ++it) {
        const int k = 2 * it;
        *ohp0 = z4; ohp0 += OH_STEP;                    // fire-and-forget zeros
        *ohp1 = z4; ohp1 += OH_STEP;

        const ulonglong2 nn2 = *(const ulonglong2*)(snrm2 + k);   // 1 LDS.128
        float lo, hi, s;

        u64 a0, a1, a2, a3, b0, b1, b2, b3;
        {   // k: rows A,B,C,D
            ulonglong2 q0 = dq[0], q1 = dq[1], q2 = dq[2], q3 = dq[3];
            a0 = nn2.x; a1 = a0; a2 = a0; a3 = a0;
            fma2(a0, muA[0], q0.x); fma2(a1, muB[0], q0.x); fma2(a2, muC[0], q0.x); fma2(a3, muD[0], q0.x);
            fma2(a0, muA[1], q0.y); fma2(a1, muB[1], q0.y); fma2(a2, muC[1], q0.y); fma2(a3, muD[1], q0.y);
            fma2(a0, muA[2], q1.x); fma2(a1, muB[2], q1.x); fma2(a2, muC[2], q1.x); fma2(a3, muD[2], q1.x);
            fma2(a0, muA[3], q1.y); fma2(a1, muB[3], q1.y); fma2(a2, muC[3], q1.y); fma2(a3, muD[3], q1.y);
            fma2(a0, muA[4], q2.x); fma2(a1, muB[4], q2.x); fma2(a2, muC[4], q2.x); fma2(a3, muD[4], q2.x);
            fma2(a0, muA[5], q2.y); fma2(a1, muB[5], q2.y); fma2(a2, muC[5], q2.y); fma2(a3, muD[5], q2.y);
            fma2(a0, muA[6], q3.x); fma2(a1, muB[6], q3.x); fma2(a2, muC[6], q3.x); fma2(a3, muD[6], q3.x);
            fma2(a0, muA[7], q3.y); fma2(a1, muB[7], q3.y); fma2(a2, muC[7], q3.y); fma2(a3, muD[7], q3.y);
        }
        {   // k+1: rows A,B,C,D
            ulonglong2 q4 = dq[4], q5 = dq[5], q6 = dq[6], q7 = dq[7];
            b0 = nn2.y; b1 = b0; b2 = b0; b3 = b0;
            fma2(b0, muA[0], q4.x); fma2(b1, muB[0], q4.x); fma2(b2, muC[0], q4.x); fma2(b3, muD[0], q4.x);
            fma2(b0, muA[1], q4.y); fma2(b1, muB[1], q4.y); fma2(b2, muC[1], q4.y); fma2(b3, muD[1], q4.y);
            fma2(b0, muA[2], q5.x); fma2(b1, muB[2], q5.x); fma2(b2, muC[2], q5.x); fma2(b3, muD[2], q5.x);
            fma2(b0, muA[3], q5.y); fma2(b1, muB[3], q5.y); fma2(b2, muC[3], q5.y); fma2(b3, muD[3], q5.y);
            fma2(b0, muA[4], q6.x); fma2(b1, muB[4], q6.x); fma2(b2, muC[4], q6.x); fma2(b3, muD[4], q6.x);
            fma2(b0, muA[5], q6.y); fma2(b1, muB[5], q6.y); fma2(b2, muC[5], q6.y); fma2(b3, muD[5], q6.y);
            fma2(b0, muA[6], q7.x); fma2(b1, muB[6], q7.x); fma2(b2, muC[6], q7.x); fma2(b3, muD[6], q7.x);
            fma2(b0, muA[7], q7.y); fma2(b1, muB[7], q7.y); fma2(b2, muC[7], q7.y); fma2(b3, muD[7], q7.y);
        }

        // R11-style @P bookkeeping; strict '>' keeps first-min ties
        unpack2(lo, hi, a0); s = lo + hi; if (s > best0) { best0 = s; i0 = k; }
        unpack2(lo, hi, b0); s = lo + hi; if (s > best0) { best0 = s; i0 = k + 1; }
        unpack2(lo, hi, a1); s = lo + hi; if (s > best1) { best1 = s; i1 = k; }
        unpack2(lo, hi, b1); s = lo + hi; if (s > best1) { best1 = s; i1 = k + 1; }
        unpack2(lo, hi, a2); s = lo + hi; if (s > best2) { best2 = s; i2 = k; }
        unpack2(lo, hi, b2); s = lo + hi; if (s > best2) { best2 = s; i2 = k + 1; }
        unpack2(lo, hi, a3); s = lo + hi; if (s > best3) { best3 = s; i3 = k; }
        unpack2(lo, hi, b3); s = lo + hi; if (s > best3) { best3 = s; i3 = k + 1; }

        dq += 8;
    }

    __syncthreads();   // all zero-stores issued before the ones land

    // ---- write z / z_embed; scatter ones (R11 epilogue) ----
    const int  rows[4] = { t, t + 128, t + 256, t + 384 };
    const int  idxs[4] = { i0, i1, i2, i3 };
    const u64* mus[4]  = { muA, muB, muC, muD };
#pragma unroll
    for (int r = 0; r < 4; ++r) {
        const float* v = sdict + idxs[r] * EE;
        size_t off = (size_t)rows[r] * (CC * EE) + c * EE;
#pragma unroll
        for (int e = 0; e < EE; e += 4) {
            float4 vv = *(const float4*)(v + e);
            float mx, my, mz, mw;
            unpack2(mx, my, mus[r][e / 2]);
            unpack2(mz, mw, mus[r][e / 2 + 1]);
            float4 zz;
            zz.x = mx + (vv.x - mx); zz.y = my + (vv.y - my);
            zz.z = mz + (vv.z - mz); zz.w = mw + (vv.w - mw);
            *(float4*)(out + Z_OFF  + off + e) = zz;
            *(float4*)(out + ZE_OFF + off + e) = vv;
        }
        out[OH_OFF + (size_t)rows[r] * (CC * KK) + (size_t)c * KK + idxs[r]] = 1.0f;
    }
}

extern "C" void kernel_launch(void* const* d_in, const int* in_sizes, int n_in,
                              void* d_out, int out_size)
{
    (void)in_sizes; (void)n_in; (void)out_size;
    const float* mu   = (const float*)d_in[0];
    const float* dict = (const float*)d_in[1];
    float* out = (float*)d_out;

    const int smem = KK * EE * 4 + KK * 8;   // 36,864 bytes
    cudaFuncSetAttribute(vq_kernel, cudaFuncAttributeMaxDynamicSharedMemorySize, smem);
    vq_kernel<<<CC, NT, smem>>>(mu, dict, out);
}

// round 17
// speedup vs baseline: 1.0317x; 1.0317x over previous
#include <cuda_runtime.h>

#define BB   512
#define CC   512
#define KK   512
#define EE   16
#define NT   128
#define NBLK 444    // 148 SMs x 3 resident

#define Z_OFF   0
#define ZE_OFF  ((size_t)BB * CC * EE)            // 4,194,304 floats
#define OH_OFF  ((size_t)2 * BB * CC * EE)        // 8,388,608 floats

typedef unsigned long long u64;

__device__ unsigned g_ctr;

__device__ __forceinline__ u64 pack2(float a, float b) {
    u64 r;
    asm("mov.b64 %0, {%1, %2};" : "=l"(r) : "f"(a), "f"(b));
    return r;
}
__device__ __forceinline__ void fma2(u64 &d, u64 a, u64 b) {
    asm("fma.rn.f32x2 %0, %1, %2, %0;" : "+l"(d) : "l"(a), "l"(b));
}
__device__ __forceinline__ void unpack2(float &lo, float &hi, u64 v) {
    asm("mov.b64 {%0, %1}, %2;" : "=f"(lo), "=f"(hi) : "l"(v));
}

// Dynamic smem (36,864 B): sdict float[KK*EE] (32 KB), snrm2 u64[KK] (4 KB)
__global__ void __launch_bounds__(NT, 3) vq_kernel(const float* __restrict__ mu,
                                                   const float* __restrict__ dict,
                                                   float* __restrict__ out)
{
    extern __shared__ float smem_f[];
    float* sdict = smem_f;
    u64*   snrm2 = (u64*)(smem_f + KK * EE);
    __shared__ int cur;

    const int t = threadIdx.x;

    for (;;) {
        if (t == 0) cur = (int)atomicAdd(&g_ctr, 1u);
        __syncthreads();
        const int c = cur;
        if (c >= CC) return;

        // ---- this thread's 4 batch rows, packed pairwise over e ----
        u64 muA[EE / 2], muB[EE / 2], muC[EE / 2], muD[EE / 2];
        {
            const float* m0 = mu + (size_t)(t)       * (CC * EE) + c * EE;
            const float* m1 = mu + (size_t)(t + 128) * (CC * EE) + c * EE;
            const float* m2 = mu + (size_t)(t + 256) * (CC * EE) + c * EE;
            const float* m3 = mu + (size_t)(t + 384) * (CC * EE) + c * EE;
#pragma unroll
            for (int e = 0; e < EE; e += 4) {
                float4 a = *(const float4*)(m0 + e);
                float4 b = *(const float4*)(m1 + e);
                float4 x = *(const float4*)(m2 + e);
                float4 y = *(const float4*)(m3 + e);
                muA[e / 2] = pack2(a.x, a.y);  muA[e / 2 + 1] = pack2(a.z, a.w);
                muB[e / 2] = pack2(b.x, b.y);  muB[e / 2 + 1] = pack2(b.z, b.w);
                muC[e / 2] = pack2(x.x, x.y);  muC[e / 2 + 1] = pack2(x.z, x.w);
                muD[e / 2] = pack2(y.x, y.y);  muD[e / 2 + 1] = pack2(y.z, y.w);
            }
        }

        // ---- dict[c] -> smem ----
        {
            const float4* g = (const float4*)(dict + (size_t)c * KK * EE);
            float4* sd4 = (float4*)sdict;
#pragma unroll 4
            for (int i = t; i < KK * EE / 4; i += NT) sd4[i] = g[i];
        }
        __syncthreads();

        // ---- snrm2[k] = (-0.5*||d_k||^2, 0) packed ----
#pragma unroll
        for (int k = t; k < KK; k += NT) {
            const float4* dv = (const float4*)(sdict + k * EE);
            float s = 0.f;
#pragma unroll
            for (int j = 0; j < 4; j++) {
                float4 v = dv[j];
                s = fmaf(v.x, v.x, s); s = fmaf(v.y, v.y, s);
                s = fmaf(v.z, v.z, s); s = fmaf(v.w, v.w, s);
            }
            snrm2[k] = pack2(-0.5f * s, 0.0f);
        }
        __syncthreads();

        // ---- one_hot zero cursors ----
        const float4 z4 = make_float4(0.f, 0.f, 0.f, 0.f);
        const size_t ROWF4 = (size_t)CC * KK / 4;
        float4* ohp0 = (float4*)(out + OH_OFF) + (size_t)c * (KK / 4) + t;
        float4* ohp1 = ohp0 + ROWF4;
        const size_t OH_STEP = 2 * ROWF4;

        // ---- main argmax loop (k-pairs): 64 FFMA2 per 5 LDS ----
        float best0 = -3.4e38f, best1 = -3.4e38f, best2 = -3.4e38f, best3 = -3.4e38f;
        int i0 = 0, i1 = 0, i2 = 0, i3 = 0;
        const ulonglong2* dq = (const ulonglong2*)sdict;

#pragma unroll 2
        for (int it = 0; it < KK / 2; ++it) {
            const int k = 2 * it;
            *ohp0 = z4; ohp0 += OH_STEP;
            *ohp1 = z4; ohp1 += OH_STEP;

            const ulonglong2 nn2 = *(const ulonglong2*)(snrm2 + k);
            float lo, hi, s;

            u64 a0, a1, a2, a3, b0, b1, b2, b3;
            {   // k: rows A,B,C,D
                ulonglong2 q0 = dq[0], q1 = dq[1], q2 = dq[2], q3 = dq[3];
                a0 = nn2.x; a1 = a0; a2 = a0; a3 = a0;
                fma2(a0, muA[0], q0.x); fma2(a1, muB[0], q0.x); fma2(a2, muC[0], q0.x); fma2(a3, muD[0], q0.x);
                fma2(a0, muA[1], q0.y); fma2(a1, muB[1], q0.y); fma2(a2, muC[1], q0.y); fma2(a3, muD[1], q0.y);
                fma2(a0, muA[2], q1.x); fma2(a1, muB[2], q1.x); fma2(a2, muC[2], q1.x); fma2(a3, muD[2], q1.x);
                fma2(a0, muA[3], q1.y); fma2(a1, muB[3], q1.y); fma2(a2, muC[3], q1.y); fma2(a3, muD[3], q1.y);
                fma2(a0, muA[4], q2.x); fma2(a1, muB[4], q2.x); fma2(a2, muC[4], q2.x); fma2(a3, muD[4], q2.x);
                fma2(a0, muA[5], q2.y); fma2(a1, muB[5], q2.y); fma2(a2, muC[5], q2.y); fma2(a3, muD[5], q2.y);
                fma2(a0, muA[6], q3.x); fma2(a1, muB[6], q3.x); fma2(a2, muC[6], q3.x); fma2(a3, muD[6], q3.x);
                fma2(a0, muA[7], q3.y); fma2(a1, muB[7], q3.y); fma2(a2, muC[7], q3.y); fma2(a3, muD[7], q3.y);
            }
            {   // k+1: rows A,B,C,D
                ulonglong2 q4 = dq[4], q5 = dq[5], q6 = dq[6], q7 = dq[7];
                b0 = nn2.y; b1 = b0; b2 = b0; b3 = b0;
                fma2(b0, muA[0], q4.x); fma2(b1, muB[0], q4.x); fma2(b2, muC[0], q4.x); fma2(b3, muD[0], q4.x);
                fma2(b0, muA[1], q4.y); fma2(b1, muB[1], q4.y); fma2(b2, muC[1], q4.y); fma2(b3, muD[1], q4.y);
                fma2(b0, muA[2], q5.x); fma2(b1, muB[2], q5.x); fma2(b2, muC[2], q5.x); fma2(b3, muD[2], q5.x);
                fma2(b0, muA[3], q5.y); fma2(b1, muB[3], q5.y); fma2(b2, muC[3], q5.y); fma2(b3, muD[3], q5.y);
                fma2(b0, muA[4], q6.x); fma2(b1, muB[4], q6.x); fma2(b2, muC[4], q6.x); fma2(b3, muD[4], q6.x);
                fma2(b0, muA[5], q6.y); fma2(b1, muB[5], q6.y); fma2(b2, muC[5], q6.y); fma2(b3, muD[5], q6.y);
                fma2(b0, muA[6], q7.x); fma2(b1, muB[6], q7.x); fma2(b2, muC[6], q7.x); fma2(b3, muD[6], q7.x);
                fma2(b0, muA[7], q7.y); fma2(b1, muB[7], q7.y); fma2(b2, muC[7], q7.y); fma2(b3, muD[7], q7.y);
            }

            // R11-style @P bookkeeping; strict '>' keeps first-min ties
            unpack2(lo, hi, a0); s = lo + hi; if (s > best0) { best0 = s; i0 = k; }
            unpack2(lo, hi, b0); s = lo + hi; if (s > best0) { best0 = s; i0 = k + 1; }
            unpack2(lo, hi, a1); s = lo + hi; if (s > best1) { best1 = s; i1 = k; }
            unpack2(lo, hi, b1); s = lo + hi; if (s > best1) { best1 = s; i1 = k + 1; }
            unpack2(lo, hi, a2); s = lo + hi; if (s > best2) { best2 = s; i2 = k; }
            unpack2(lo, hi, b2); s = lo + hi; if (s > best2) { best2 = s; i2 = k + 1; }
            unpack2(lo, hi, a3); s = lo + hi; if (s > best3) { best3 = s; i3 = k; }
            unpack2(lo, hi, b3); s = lo + hi; if (s > best3) { best3 = s; i3 = k + 1; }

            dq += 8;
        }

        __syncthreads();   // this c's zero-stores issued before its ones land

        // ---- write z / z_embed; scatter ones ----
        const int  rows[4] = { t, t + 128, t + 256, t + 384 };
        const int  idxs[4] = { i0, i1, i2, i3 };
        const u64* mus[4]  = { muA, muB, muC, muD };
#pragma unroll
        for (int r = 0; r < 4; ++r) {
            const float* v = sdict + idxs[r] * EE;
            size_t off = (size_t)rows[r] * (CC * EE) + c * EE;
#pragma unroll
            for (int e = 0; e < EE; e += 4) {
                float4 vv = *(const float4*)(v + e);
                float mx, my, mz, mw;
                unpack2(mx, my, mus[r][e / 2]);
                unpack2(mz, mw, mus[r][e / 2 + 1]);
                float4 zz;
                zz.x = mx + (vv.x - mx); zz.y = my + (vv.y - my);
                zz.z = mz + (vv.z - mz); zz.w = mw + (vv.w - mw);
                *(float4*)(out + Z_OFF  + off + e) = zz;
                *(float4*)(out + ZE_OFF + off + e) = vv;
            }
            out[OH_OFF + (size_t)rows[r] * (CC * KK) + (size_t)c * KK + idxs[r]] = 1.0f;
        }

        __syncthreads();   // epilogue's sdict reads done before next c reloads
    }
}

extern "C" void kernel_launch(void* const* d_in, const int* in_sizes, int n_in,
                              void* d_out, int out_size)
{
    (void)in_sizes; (void)n_in; (void)out_size;
    const float* mu   = (const float*)d_in[0];
    const float* dict = (const float*)d_in[1];
    float* out = (float*)d_out;

    unsigned* ctr = nullptr;
    cudaGetSymbolAddress((void**)&ctr, g_ctr);
    cudaMemsetAsync(ctr, 0, sizeof(unsigned), 0);

    const int smem = KK * EE * 4 + KK * 8;   // 36,864 bytes
    cudaFuncSetAttribute(vq_kernel, cudaFuncAttributeMaxDynamicSharedMemorySize, smem);
    vq_kernel<<<NBLK, NT, smem>>>(mu, dict, out);
}